// round 15
// baseline (speedup 1.0000x reference)
#include <cuda_runtime.h>

// AutoregressiveBisectionInverter — closed-form inversion, R15.
// R13 + deeper staging pipeline (two stager warps, three join points).
//
// W strictly lower triangular => bisected function is linear in x_i:
//   x_i = (y_i - sum_{j<i} W[i,j] tanh(x_j)) / softplus(a_i)
// Pre-scale Wsh[i][j] = -W[i,j]/softplus(a_i), y'_i = y_i/softplus(a_i):
//   x_i = y'_i + sum_{j<i} Wsh[i,j] * tanh(x_j)
//
// One warp per batch row; lane l accumulates dims {l, l+32}. Wsh[l][j]=0 for
// j>=l => lane l's accumulator FREEZES at x_l; final acc IS the output; acc0
// (dims 0..31) stored at mid-loop so the STG drain overlaps chunks 8..15.
//
// Staging pipeline (chunk c touches W cols <= 4c+3 only):
//   warps 0-3 (compute): stage cols  0..15 (2 f4/thr), bar.sync 2 (128), chain
//   warp 4:              stage cols 16..31 (8 f4/lane), bar.arrive 1 (160)
//   warp 5:              stage cols 32..63 (16 f4/lane), bar.arrive 3 (160)
//   compute joins bar 1 at chunk 4, bar 3 at chunk 8.

#define AD 64
#define AB 512
#define ROWS_PER_BLOCK 4
#define NCOMPUTE 128
#define NTHREADS 192
#define WSTRIDE 68

__device__ __forceinline__ float tanh_fast(float x) {
    float r;
    asm("tanh.approx.f32 %0, %1;" : "=f"(r) : "f"(x));
    return r;
}

__device__ __forceinline__ float inv_softplus(float x) {
    // 1 / log(1 + e^x), MUFU-only; x in [0.5, 1.5].
    return __fdividef(1.0f, __logf(1.0f + __expf(x)));
}

__global__ __launch_bounds__(NTHREADS, 1)
void arbi_kernel(const float* __restrict__ y,
                 const float* __restrict__ a,
                 const float* __restrict__ W,
                 float* __restrict__ out)
{
    __shared__ float invs_sh[AD];
    __shared__ __align__(16) float Wsh[AD * WSTRIDE];

    const int tid  = threadIdx.x;
    const int lane = tid & 31;
    const int wid  = tid >> 5;

    const float4* W4 = (const float4*)W;   // 16 float4 per row

    // ---- Phase 1: issue all independent LDGs, compute invs, one barrier ----
    float yv0 = 0.f, yv1 = 0.f;
    float4 wvc[2];                          // compute: cols 0..15
    float4 wv4[8];                          // warp 4: cols 16..31
    float4 wv5[16];                         // warp 5: cols 32..63
    int row = 0;

    if (wid < 4) {
        row = blockIdx.x * ROWS_PER_BLOCK + wid;
        const float* yr = y + row * AD;
        yv0 = yr[lane];
        yv1 = yr[lane + 32];
        #pragma unroll
        for (int k = 0; k < 2; ++k) {
            const int idx = tid + NCOMPUTE * k;      // 0..255
            const int r   = idx >> 2;                // row 0..63
            const int c4  = idx & 3;                 // f4-col 0..3 (cols 0..15)
            wvc[k] = W4[r * 16 + c4];
        }
    } else if (wid == 4) {
        #pragma unroll
        for (int k = 0; k < 8; ++k) {
            const int idx = lane + 32 * k;           // 0..255
            const int r   = idx >> 2;
            const int c4  = 4 + (idx & 3);           // f4-col 4..7 (cols 16..31)
            wv4[k] = W4[r * 16 + c4];
        }
    } else {
        #pragma unroll
        for (int k = 0; k < 16; ++k) {
            const int idx = lane + 32 * k;           // 0..511
            const int r   = idx >> 3;
            const int c4  = 8 + (idx & 7);           // f4-col 8..15 (cols 32..63)
            wv5[k] = W4[r * 16 + c4];
        }
    }

    if (tid < AD) {
        invs_sh[tid] = inv_softplus(a[tid]);
    }
    __syncthreads();   // all 192: invs_sh visible; W LDGs in flight

    if (wid == 4) {
        // ---- Stager A: cols 16..31, ready before chunk 4 ----
        #pragma unroll
        for (int k = 0; k < 8; ++k) {
            const int idx = lane + 32 * k;
            const int r   = idx >> 2;
            const int c4  = 4 + (idx & 3);
            const float sc = -invs_sh[r];
            float4 sv;
            sv.x = wv4[k].x * sc; sv.y = wv4[k].y * sc;
            sv.z = wv4[k].z * sc; sv.w = wv4[k].w * sc;
            *(float4*)&Wsh[r * WSTRIDE + c4 * 4] = sv;
        }
        asm volatile("bar.arrive 1, 160;" ::: "memory");
        return;
    }
    if (wid == 5) {
        // ---- Stager B: cols 32..63, ready before chunk 8 ----
        #pragma unroll
        for (int k = 0; k < 16; ++k) {
            const int idx = lane + 32 * k;
            const int r   = idx >> 3;
            const int c4  = 8 + (idx & 7);
            const float sc = -invs_sh[r];
            float4 sv;
            sv.x = wv5[k].x * sc; sv.y = wv5[k].y * sc;
            sv.z = wv5[k].z * sc; sv.w = wv5[k].w * sc;
            *(float4*)&Wsh[r * WSTRIDE + c4 * 4] = sv;
        }
        asm volatile("bar.arrive 3, 160;" ::: "memory");
        return;
    }

    // ---- Compute path ----
    const float inv_l0 = invs_sh[lane];
    const float inv_l1 = invs_sh[lane + 32];
    float acc0 = yv0 * inv_l0;
    float acc1 = yv1 * inv_l1;

    // Chunk-0 partials issued early; shfl latency overlaps the STS below.
    float b0 = __shfl_sync(0xffffffffu, acc0, 0);
    float b1 = __shfl_sync(0xffffffffu, acc0, 1);
    float b2 = __shfl_sync(0xffffffffu, acc0, 2);
    float b3 = __shfl_sync(0xffffffffu, acc0, 3);

    // Scale + store cols 0..15 (2 f4/thread).
    #pragma unroll
    for (int k = 0; k < 2; ++k) {
        const int idx = tid + NCOMPUTE * k;
        const int r   = idx >> 2;
        const int c4  = idx & 3;
        const float sc = -invs_sh[r];
        float4 sv;
        sv.x = wvc[k].x * sc; sv.y = wvc[k].y * sc;
        sv.z = wvc[k].z * sc; sv.w = wvc[k].w * sc;
        *(float4*)&Wsh[r * WSTRIDE + c4 * 4] = sv;
    }
    // Compute-only barrier: cols 0..15 of Wsh ready.
    asm volatile("bar.sync 2, %0;" :: "n"(NCOMPUTE) : "memory");

    #pragma unroll
    for (int c = 0; c < 16; ++c) {
        const int j = 4 * c;

        if (c == 4) {   // join stager A: cols 16..31 ready
            asm volatile("bar.sync 1, 160;" ::: "memory");
        }
        if (c == 8) {   // join stager B: cols 32..63 ready
            asm volatile("bar.sync 3, 160;" ::: "memory");
        }

        // Lane-uniform diag-band weights (broadcast LDS; pairs as v2).
        const float  w10    = Wsh[(j + 1) * WSTRIDE + j];
        const float2 w20_21 = *(const float2*)&Wsh[(j + 2) * WSTRIDE + j];
        const float2 w30_31 = *(const float2*)&Wsh[(j + 3) * WSTRIDE + j];
        const float  w32    = Wsh[(j + 3) * WSTRIDE + j + 2];
        float2 w4 = {0.f, 0.f}, w5 = {0.f, 0.f};
        float2 w6 = {0.f, 0.f}, w7 = {0.f, 0.f};
        if (c < 15) {
            w4 = *(const float2*)&Wsh[(j + 4) * WSTRIDE + j + 2];
            w5 = *(const float2*)&Wsh[(j + 5) * WSTRIDE + j + 2];
            w6 = *(const float2*)&Wsh[(j + 6) * WSTRIDE + j + 2];
            w7 = *(const float2*)&Wsh[(j + 7) * WSTRIDE + j + 2];
        }
        // Per-lane acc-update weights for this chunk's 4 columns (LDS.128).
        const float4 wla = *(const float4*)&Wsh[lane * WSTRIDE + j];
        const float4 wlb = *(const float4*)&Wsh[(lane + 32) * WSTRIDE + j];

        // ---- dim j ----
        const float t0 = tanh_fast(b0);

        // ---- dim j+1 ----
        const float x1 = fmaf(w10, t0, b1);
        const float t1 = tanh_fast(x1);

        acc0 = fmaf(wla.x, t0, acc0);
        acc1 = fmaf(wlb.x, t0, acc1);
        acc0 = fmaf(wla.y, t1, acc0);
        acc1 = fmaf(wlb.y, t1, acc1);

        // Early shfl of next chunk's partials (contain t_{<=j+1}); missing
        // t_{j+2}, t_{j+3} replayed below on all lanes.
        float bp0 = 0.f, bp1 = 0.f, bp2 = 0.f, bp3 = 0.f;
        if (c < 15) {
            const float src = (j + 4 < 32) ? acc0 : acc1;
            bp0 = __shfl_sync(0xffffffffu, src, (j + 4) & 31);
            bp1 = __shfl_sync(0xffffffffu, src, (j + 5) & 31);
            bp2 = __shfl_sync(0xffffffffu, src, (j + 6) & 31);
            bp3 = __shfl_sync(0xffffffffu, src, (j + 7) & 31);
        }

        // ---- dim j+2 ----
        const float x2 = fmaf(w20_21.y, t1, fmaf(w20_21.x, t0, b2));
        const float t2 = tanh_fast(x2);

        acc0 = fmaf(wla.z, t2, acc0);
        acc1 = fmaf(wlb.z, t2, acc1);

        // ---- dim j+3 ----
        const float x3 = fmaf(w32, t2,
                        fmaf(w30_31.y, t1, fmaf(w30_31.x, t0, b3)));
        const float t3 = tanh_fast(x3);

        acc0 = fmaf(wla.w, t3, acc0);
        acc1 = fmaf(wlb.w, t3, acc1);

        // Replay t_{j+2}, t_{j+3} into the early-shfl'd partials.
        if (c < 15) {
            b0 = fmaf(w4.y, t3, fmaf(w4.x, t2, bp0));
            b1 = fmaf(w5.y, t3, fmaf(w5.x, t2, bp1));
            b2 = fmaf(w6.y, t3, fmaf(w6.x, t2, bp2));
            b3 = fmaf(w7.y, t3, fmaf(w7.x, t2, bp3));
        }

        // After chunk 7 (cols 0..31 applied), acc0 is frozen for all lanes
        // -> store early; STG drain overlaps chunks 8..15.
        if (c == 7) {
            out[row * AD + lane] = acc0;
        }
    }

    // Dims 32..63 final after the last chunk.
    out[row * AD + lane + 32] = acc1;
}

extern "C" void kernel_launch(void* const* d_in, const int* in_sizes, int n_in,
                              void* d_out, int out_size)
{
    const float* y = (const float*)d_in[0];   // (512, 64)
    const float* a = (const float*)d_in[1];   // (64,)
    const float* W = (const float*)d_in[2];   // (64, 64)
    float* out = (float*)d_out;               // (512, 64)

    arbi_kernel<<<AB / ROWS_PER_BLOCK, NTHREADS>>>(y, a, W, out);
}

// round 16
// speedup vs baseline: 1.0385x; 1.0385x over previous
#include <cuda_runtime.h>

// AutoregressiveBisectionInverter — closed-form inversion, R16.
// R13 structure (champion: ncu 5.344) + fully-decoupled stager warp.
//
// W strictly lower triangular => bisected function is linear in x_i:
//   x_i = (y_i - sum_{j<i} W[i,j] tanh(x_j)) / softplus(a_i)
// Pre-scale Wsh[i][j] = -W[i,j]/softplus(a_i), y'_i = y_i/softplus(a_i):
//   x_i = y'_i + sum_{j<i} Wsh[i,j] * tanh(x_j)
//
// One warp per batch row; lane l accumulates dims {l, l+32}. Wsh[l][j]=0 for
// j>=l => lane l's accumulator FREEZES at x_l; final acc IS the output; acc0
// (dims 0..31) stored at mid-loop so the STG drain overlaps chunks 8..15.
//
// Warp specialization (chunk c touches W cols <= 4c+3 only):
//   warps 0-3 (compute): stage cols 0..31 (4 f4/thr); named bars 2,4 (128);
//                        chain; join bar 1 (160) at chunk 8.
//   warp 4 (stager):     stage cols 32..63 (16 f4/lane); computes its own
//                        softplus inverses from a[] (no invs_sh dependency,
//                        participates in NO compute barrier — removes the
//                        straggler from compute's barrier release);
//                        bar.arrive 1 (160) when done.

#define AD 64
#define AB 512
#define ROWS_PER_BLOCK 4
#define NCOMPUTE 128
#define NTHREADS 160
#define WSTRIDE 68

__device__ __forceinline__ float tanh_fast(float x) {
    float r;
    asm("tanh.approx.f32 %0, %1;" : "=f"(r) : "f"(x));
    return r;
}

__device__ __forceinline__ float inv_softplus(float x) {
    // 1 / log(1 + e^x), MUFU-only; x in [0.5, 1.5].
    return __fdividef(1.0f, __logf(1.0f + __expf(x)));
}

__global__ __launch_bounds__(NTHREADS, 1)
void arbi_kernel(const float* __restrict__ y,
                 const float* __restrict__ a,
                 const float* __restrict__ W,
                 float* __restrict__ out)
{
    __shared__ float invs_sh[AD];
    __shared__ __align__(16) float Wsh[AD * WSTRIDE];

    const int tid  = threadIdx.x;
    const int lane = tid & 31;
    const int wid  = tid >> 5;

    const float4* W4 = (const float4*)W;   // 16 float4 per row

    if (wid == 4) {
        // ---- Stager warp: cols 32..63, fully decoupled ----
        // Issue all LDGs first (W f4s + the a values for its rows).
        float4 wv[16];
        float  av[16];
        #pragma unroll
        for (int k = 0; k < 16; ++k) {
            const int idx = lane + 32 * k;           // 0..511
            const int r   = idx >> 3;                // row 0..63
            const int c4  = 8 + (idx & 7);           // f4-col 8..15 (cols 32..63)
            wv[k] = W4[r * 16 + c4];
        }
        #pragma unroll
        for (int k = 0; k < 16; ++k) {
            av[k] = a[(lane + 32 * k) >> 3];
        }
        // Scale with self-computed inverses (redundant MUFU, off-path).
        #pragma unroll
        for (int k = 0; k < 16; ++k) {
            const int idx = lane + 32 * k;
            const int r   = idx >> 3;
            const int c4  = 8 + (idx & 7);
            const float sc = -inv_softplus(av[k]);
            float4 sv;
            sv.x = wv[k].x * sc; sv.y = wv[k].y * sc;
            sv.z = wv[k].z * sc; sv.w = wv[k].w * sc;
            *(float4*)&Wsh[r * WSTRIDE + c4 * 4] = sv;
        }
        asm volatile("bar.arrive 1, %0;" :: "n"(NTHREADS) : "memory");
        return;
    }

    // ---- Compute warps 0..3: one batch row each ----
    const int row = blockIdx.x * ROWS_PER_BLOCK + wid;
    const float* yr = y + row * AD;
    const float yv0 = yr[lane];
    const float yv1 = yr[lane + 32];

    float4 wvc[4];                                   // cols 0..31
    #pragma unroll
    for (int k = 0; k < 4; ++k) {
        const int idx = tid + NCOMPUTE * k;          // 0..511
        const int r   = idx >> 3;
        const int c4  = idx & 7;                     // f4-col 0..7
        wvc[k] = W4[r * 16 + c4];
    }

    if (tid < AD) {
        invs_sh[tid] = inv_softplus(a[tid]);
    }
    // Compute-only barrier: invs_sh ready (stager NOT involved).
    asm volatile("bar.sync 2, %0;" :: "n"(NCOMPUTE) : "memory");

    const float inv_l0 = invs_sh[lane];
    const float inv_l1 = invs_sh[lane + 32];
    float acc0 = yv0 * inv_l0;
    float acc1 = yv1 * inv_l1;

    // Chunk-0 partials issued early; shfl latency overlaps the STS below.
    float b0 = __shfl_sync(0xffffffffu, acc0, 0);
    float b1 = __shfl_sync(0xffffffffu, acc0, 1);
    float b2 = __shfl_sync(0xffffffffu, acc0, 2);
    float b3 = __shfl_sync(0xffffffffu, acc0, 3);

    // Scale + store cols 0..31 (4 f4/thread).
    #pragma unroll
    for (int k = 0; k < 4; ++k) {
        const int idx = tid + NCOMPUTE * k;
        const int r   = idx >> 3;
        const int c4  = idx & 7;
        const float sc = -invs_sh[r];
        float4 sv;
        sv.x = wvc[k].x * sc; sv.y = wvc[k].y * sc;
        sv.z = wvc[k].z * sc; sv.w = wvc[k].w * sc;
        *(float4*)&Wsh[r * WSTRIDE + c4 * 4] = sv;
    }
    // Compute-only barrier: Wsh cols 0..31 ready.
    asm volatile("bar.sync 4, %0;" :: "n"(NCOMPUTE) : "memory");

    #pragma unroll
    for (int c = 0; c < 16; ++c) {
        const int j = 4 * c;

        if (c == 8) {
            // Join with stager: Wsh cols 32..63 ready.
            asm volatile("bar.sync 1, %0;" :: "n"(NTHREADS) : "memory");
        }

        // Lane-uniform diag-band weights (broadcast LDS; pairs as v2).
        const float  w10    = Wsh[(j + 1) * WSTRIDE + j];
        const float2 w20_21 = *(const float2*)&Wsh[(j + 2) * WSTRIDE + j];
        const float2 w30_31 = *(const float2*)&Wsh[(j + 3) * WSTRIDE + j];
        const float  w32    = Wsh[(j + 3) * WSTRIDE + j + 2];
        float2 w4 = {0.f, 0.f}, w5 = {0.f, 0.f};
        float2 w6 = {0.f, 0.f}, w7 = {0.f, 0.f};
        if (c < 15) {
            w4 = *(const float2*)&Wsh[(j + 4) * WSTRIDE + j + 2];
            w5 = *(const float2*)&Wsh[(j + 5) * WSTRIDE + j + 2];
            w6 = *(const float2*)&Wsh[(j + 6) * WSTRIDE + j + 2];
            w7 = *(const float2*)&Wsh[(j + 7) * WSTRIDE + j + 2];
        }
        // Per-lane acc-update weights for this chunk's 4 columns (LDS.128).
        const float4 wla = *(const float4*)&Wsh[lane * WSTRIDE + j];
        const float4 wlb = *(const float4*)&Wsh[(lane + 32) * WSTRIDE + j];

        // ---- dim j ----
        const float t0 = tanh_fast(b0);

        // ---- dim j+1 ----
        const float x1 = fmaf(w10, t0, b1);
        const float t1 = tanh_fast(x1);

        acc0 = fmaf(wla.x, t0, acc0);
        acc1 = fmaf(wlb.x, t0, acc1);
        acc0 = fmaf(wla.y, t1, acc0);
        acc1 = fmaf(wlb.y, t1, acc1);

        // Early shfl of next chunk's partials (contain t_{<=j+1}); missing
        // t_{j+2}, t_{j+3} replayed below on all lanes.
        float bp0 = 0.f, bp1 = 0.f, bp2 = 0.f, bp3 = 0.f;
        if (c < 15) {
            const float src = (j + 4 < 32) ? acc0 : acc1;
            bp0 = __shfl_sync(0xffffffffu, src, (j + 4) & 31);
            bp1 = __shfl_sync(0xffffffffu, src, (j + 5) & 31);
            bp2 = __shfl_sync(0xffffffffu, src, (j + 6) & 31);
            bp3 = __shfl_sync(0xffffffffu, src, (j + 7) & 31);
        }

        // ---- dim j+2 ----
        const float x2 = fmaf(w20_21.y, t1, fmaf(w20_21.x, t0, b2));
        const float t2 = tanh_fast(x2);

        acc0 = fmaf(wla.z, t2, acc0);
        acc1 = fmaf(wlb.z, t2, acc1);

        // ---- dim j+3 ----
        const float x3 = fmaf(w32, t2,
                        fmaf(w30_31.y, t1, fmaf(w30_31.x, t0, b3)));
        const float t3 = tanh_fast(x3);

        acc0 = fmaf(wla.w, t3, acc0);
        acc1 = fmaf(wlb.w, t3, acc1);

        // Replay t_{j+2}, t_{j+3} into the early-shfl'd partials.
        if (c < 15) {
            b0 = fmaf(w4.y, t3, fmaf(w4.x, t2, bp0));
            b1 = fmaf(w5.y, t3, fmaf(w5.x, t2, bp1));
            b2 = fmaf(w6.y, t3, fmaf(w6.x, t2, bp2));
            b3 = fmaf(w7.y, t3, fmaf(w7.x, t2, bp3));
        }

        // After chunk 7 (cols 0..31 applied), acc0 is frozen for all lanes
        // -> store early; STG drain overlaps chunks 8..15.
        if (c == 7) {
            out[row * AD + lane] = acc0;
        }
    }

    // Dims 32..63 final after the last chunk.
    out[row * AD + lane + 32] = acc1;
}

extern "C" void kernel_launch(void* const* d_in, const int* in_sizes, int n_in,
                              void* d_out, int out_size)
{
    const float* y = (const float*)d_in[0];   // (512, 64)
    const float* a = (const float*)d_in[1];   // (64,)
    const float* W = (const float*)d_in[2];   // (64, 64)
    float* out = (float*)d_out;               // (512, 64)

    arbi_kernel<<<AB / ROWS_PER_BLOCK, NTHREADS>>>(y, a, W, out);
}